// round 2
// baseline (speedup 1.0000x reference)
#include <cuda_runtime.h>
#include <math.h>

// ---------------------------------------------------------------------------
// GRU LM: T=128, B=64, E=H=512, V=10000, 2 layers.
//
// Structure:
//   1. gather embeddings (8192 x 512)
//   2. gates_x(l=0) = emb @ W_x0 + b  (big GEMM, 8192x1536x512)
//   3. layer-0 recurrence: per t, phaseA (h@U_h + sigmoid -> rh,z),
//      phaseB ((rh)@U_ht + tanh -> h update), storing h[t] for all t
//   4. fc0 batched over all t (8192x512x512, NT)
//   5. gates_x(l=1) big GEMM
//   6. layer-1 recurrence
//   7. fc1 batched
//   8. decoder logits = inp @ dec_W^T + dec_b (8192x10000x512, NT)
// ---------------------------------------------------------------------------

#define TT   128
#define BB   64
#define HH   512
#define VV   10000
#define MALL (TT * BB)   // 8192

// scratch (device globals: no allocation allowed)
__device__ float g_emb [MALL * HH];
__device__ float g_gx  [MALL * 3 * HH];
__device__ float g_inp [MALL * HH];
__device__ float g_hall[MALL * HH];
__device__ float g_hcur[BB * HH];
__device__ float g_z   [BB * HH];
__device__ float g_rh  [BB * HH];

// ---------------------------------------------------------------------------
// Embedding gather: one block per (t,b) row.
// ---------------------------------------------------------------------------
__global__ void k_gather(const int* __restrict__ inp, const float* __restrict__ tbl) {
    int i   = blockIdx.x;              // 0..8191
    int row = inp[i];
    const float4* src = reinterpret_cast<const float4*>(tbl + (size_t)row * HH);
    float4*       dst = reinterpret_cast<float4*>(g_emb + (size_t)i * HH);
    for (int j = threadIdx.x; j < HH / 4; j += blockDim.x) dst[j] = src[j];
}

// ---------------------------------------------------------------------------
// Big fp32 GEMM: C[M,N] = A[M,K] @ op(B) + bias
//   NT=false: B is (K,N) row-major   (W_x, U-style weights)
//   NT=true : B is (N,K) row-major   (fc_W, dec_W used transposed)
// Tiles: BM=128, BN=64, BK=16, 256 threads, 8x4 per thread.
// M must be a multiple of 128 and K of 16 (true here). N may be ragged
// at float4 granularity (10000 % 4 == 0).
// ---------------------------------------------------------------------------
template <bool NT>
__global__ __launch_bounds__(256) void k_gemm(const float* __restrict__ A,
                                              const float* __restrict__ Bm,
                                              const float* __restrict__ bias,
                                              float* __restrict__ C,
                                              int M, int N, int K) {
    __shared__ float sA[16][128];
    __shared__ float sB[16][64];
    int tid = threadIdx.x;
    int tx  = tid & 15;     // n quad
    int ty  = tid >> 4;     // m octet
    int m0  = blockIdx.y * 128;
    int n0  = blockIdx.x * 64;

    float acc[8][4];
#pragma unroll
    for (int i = 0; i < 8; i++)
#pragma unroll
        for (int j = 0; j < 4; j++) acc[i][j] = 0.f;

    for (int k0 = 0; k0 < K; k0 += 16) {
        // A tile (128x16), stored k-major (transposed)
#pragma unroll
        for (int i = 0; i < 2; i++) {
            int idx = tid + i * 256;       // 0..511 float4s
            int r   = idx >> 2;            // 0..127
            int c4  = idx & 3;             // 0..3
            float4 v = *reinterpret_cast<const float4*>(
                &A[(size_t)(m0 + r) * K + k0 + c4 * 4]);
            sA[c4 * 4 + 0][r] = v.x;
            sA[c4 * 4 + 1][r] = v.y;
            sA[c4 * 4 + 2][r] = v.z;
            sA[c4 * 4 + 3][r] = v.w;
        }
        // B tile (16x64)
        if (!NT) {
            int r  = tid >> 4;             // k
            int c4 = tid & 15;             // n quad
            int n  = n0 + c4 * 4;
            float4 v = make_float4(0.f, 0.f, 0.f, 0.f);
            if (n < N)
                v = *reinterpret_cast<const float4*>(&Bm[(size_t)(k0 + r) * N + n]);
            *reinterpret_cast<float4*>(&sB[r][c4 * 4]) = v;
        } else {
            int r  = tid >> 2;             // n within tile (0..63)
            int c4 = tid & 3;              // k quad
            int n  = n0 + r;
            float4 v = make_float4(0.f, 0.f, 0.f, 0.f);
            if (n < N)
                v = *reinterpret_cast<const float4*>(&Bm[(size_t)n * K + k0 + c4 * 4]);
            sB[c4 * 4 + 0][r] = v.x;
            sB[c4 * 4 + 1][r] = v.y;
            sB[c4 * 4 + 2][r] = v.z;
            sB[c4 * 4 + 3][r] = v.w;
        }
        __syncthreads();

#pragma unroll
        for (int k = 0; k < 16; k++) {
            float4 b  = *reinterpret_cast<float4*>(&sB[k][tx * 4]);
            float4 a0 = *reinterpret_cast<float4*>(&sA[k][ty * 8]);
            float4 a1 = *reinterpret_cast<float4*>(&sA[k][ty * 8 + 4]);
            float av[8] = {a0.x, a0.y, a0.z, a0.w, a1.x, a1.y, a1.z, a1.w};
            float bv[4] = {b.x, b.y, b.z, b.w};
#pragma unroll
            for (int i = 0; i < 8; i++)
#pragma unroll
                for (int j = 0; j < 4; j++) acc[i][j] += av[i] * bv[j];
        }
        __syncthreads();
    }

    int n = n0 + tx * 4;
    if (n < N) {
        float4 bv = make_float4(0.f, 0.f, 0.f, 0.f);
        if (bias) bv = *reinterpret_cast<const float4*>(&bias[n]);
#pragma unroll
        for (int i = 0; i < 8; i++) {
            int row = m0 + ty * 8 + i;
            float4 o;
            o.x = acc[i][0] + bv.x;
            o.y = acc[i][1] + bv.y;
            o.z = acc[i][2] + bv.z;
            o.w = acc[i][3] + bv.w;
            *reinterpret_cast<float4*>(&C[(size_t)row * N + n]) = o;
        }
    }
}

// ---------------------------------------------------------------------------
// Phase A (per t, layer): pre[b,n'] = gx[b,n'] + sum_j h[b,j] * U_h[j,n']
// over n' in [0,1024); n'<512 -> r gate (emit rh = sig*h), else z gate.
// Grid (1024/32, 64/16) = (32,4), 128 threads, thread = 1 row x 4 cols.
// ---------------------------------------------------------------------------
__global__ __launch_bounds__(128) void k_phaseA(const float* __restrict__ Uh, int t) {
    __shared__ float sA[16][68];   // h rows (padded vs bank conflicts)
    __shared__ float sB[64][32];   // U tile
    int tid = threadIdx.x;
    int tx  = tid & 7;      // col quad
    int ty  = tid >> 3;     // row 0..15
    int m0  = blockIdx.y * 16;
    int n0  = blockIdx.x * 32;

    float acc[4] = {0.f, 0.f, 0.f, 0.f};
    for (int k0 = 0; k0 < HH; k0 += 64) {
#pragma unroll
        for (int i = 0; i < 2; i++) {
            int idx = tid + i * 128;       // 0..255 float4s (16x64)
            int r = idx >> 4, c = idx & 15;
            *reinterpret_cast<float4*>(&sA[r][c * 4]) =
                *reinterpret_cast<const float4*>(&g_hcur[(size_t)(m0 + r) * HH + k0 + c * 4]);
        }
#pragma unroll
        for (int i = 0; i < 4; i++) {
            int idx = tid + i * 128;       // 0..511 float4s (64x32)
            int r = idx >> 3, c = idx & 7;
            *reinterpret_cast<float4*>(&sB[r][c * 4]) =
                *reinterpret_cast<const float4*>(&Uh[(size_t)(k0 + r) * (2 * HH) + n0 + c * 4]);
        }
        __syncthreads();
#pragma unroll
        for (int k = 0; k < 64; k++) {
            float  a = sA[ty][k];
            float4 b = *reinterpret_cast<float4*>(&sB[k][tx * 4]);
            acc[0] += a * b.x;
            acc[1] += a * b.y;
            acc[2] += a * b.z;
            acc[3] += a * b.w;
        }
        __syncthreads();
    }

    int row = m0 + ty;
    const float* gx = g_gx + ((size_t)t * BB + row) * (3 * HH);
#pragma unroll
    for (int q = 0; q < 4; q++) {
        int n = n0 + tx * 4 + q;           // 0..1023
        float pre = gx[n] + acc[q];        // n<512: Wrx col n; n>=512: Wzx col n
        float s = 1.f / (1.f + expf(-pre));
        if (n < HH)
            g_rh[row * HH + n] = s * g_hcur[row * HH + n];
        else
            g_z[row * HH + n - HH] = s;
    }
}

// ---------------------------------------------------------------------------
// Phase B (per t, layer): c = sum_j rh[b,j]*U_ht[j,n]; ht = tanh(Whx+c);
// h_new = (1-z)*h + z*ht ; write g_hcur and g_hall[t].
// Grid (512/16, 64/16) = (32,4), 128 threads, thread = 1 row x 2 cols.
// ---------------------------------------------------------------------------
__global__ __launch_bounds__(128) void k_phaseB(const float* __restrict__ Uht, int t) {
    __shared__ float sA[16][68];
    __shared__ float sB[64][16];
    int tid = threadIdx.x;
    int tx  = tid & 7;
    int ty  = tid >> 3;
    int m0  = blockIdx.y * 16;
    int n0  = blockIdx.x * 16;

    float acc[2] = {0.f, 0.f};
    for (int k0 = 0; k0 < HH; k0 += 64) {
#pragma unroll
        for (int i = 0; i < 2; i++) {
            int idx = tid + i * 128;
            int r = idx >> 4, c = idx & 15;
            *reinterpret_cast<float4*>(&sA[r][c * 4]) =
                *reinterpret_cast<const float4*>(&g_rh[(size_t)(m0 + r) * HH + k0 + c * 4]);
        }
#pragma unroll
        for (int i = 0; i < 2; i++) {
            int idx = tid + i * 128;       // 0..255 float4s (64x16)
            int r = idx >> 2, c = idx & 3;
            *reinterpret_cast<float4*>(&sB[r][c * 4]) =
                *reinterpret_cast<const float4*>(&Uht[(size_t)(k0 + r) * HH + n0 + c * 4]);
        }
        __syncthreads();
#pragma unroll
        for (int k = 0; k < 64; k++) {
            float  a = sA[ty][k];
            float2 b = *reinterpret_cast<float2*>(&sB[k][tx * 2]);
            acc[0] += a * b.x;
            acc[1] += a * b.y;
        }
        __syncthreads();
    }

    int row = m0 + ty;
    const float* gx = g_gx + ((size_t)t * BB + row) * (3 * HH) + 2 * HH;
#pragma unroll
    for (int q = 0; q < 2; q++) {
        int n    = n0 + tx * 2 + q;
        float pre  = gx[n] + acc[q];
        float htil = tanhf(pre);
        int   idx  = row * HH + n;
        float z = g_z[idx];
        float h = g_hcur[idx];
        float hn = (1.f - z) * h + z * htil;
        g_hcur[idx] = hn;
        g_hall[((size_t)t * BB + row) * HH + n] = hn;
    }
}

// ---------------------------------------------------------------------------
extern "C" void kernel_launch(void* const* d_in, const int* in_sizes, int n_in,
                              void* d_out, int out_size) {
    const int*   inputs    = (const int*)  d_in[0];
    const float* hidden    = (const float*)d_in[1];
    const float* emb_table = (const float*)d_in[2];
    const float* W_x       = (const float*)d_in[3];
    const float* U_h       = (const float*)d_in[4];
    const float* U_ht      = (const float*)d_in[5];
    const float* b_rzh     = (const float*)d_in[6];
    const float* fc_W      = (const float*)d_in[7];
    const float* fc_b      = (const float*)d_in[8];
    const float* dec_W     = (const float*)d_in[9];
    const float* dec_b     = (const float*)d_in[10];
    float* out = (float*)d_out;

    float *p_emb, *p_gx, *p_inp, *p_hall, *p_hcur;
    cudaGetSymbolAddress((void**)&p_emb,  g_emb);
    cudaGetSymbolAddress((void**)&p_gx,   g_gx);
    cudaGetSymbolAddress((void**)&p_inp,  g_inp);
    cudaGetSymbolAddress((void**)&p_hall, g_hall);
    cudaGetSymbolAddress((void**)&p_hcur, g_hcur);

    // 1) embeddings
    k_gather<<<MALL, 128>>>(inputs, emb_table);

    // 2) gates_x for layer 0 over all timesteps
    k_gemm<false><<<dim3((3 * HH) / 64, MALL / 128), 256>>>(
        p_emb, W_x, b_rzh, p_gx, MALL, 3 * HH, HH);

    long long need = (long long)TT * BB * VV + 2LL * BB * HH;

    for (int l = 0; l < 2; l++) {
        cudaMemcpyAsync(p_hcur, hidden + (size_t)l * BB * HH,
                        (size_t)BB * HH * sizeof(float), cudaMemcpyDeviceToDevice);
        const float* Uh_l  = U_h  + (size_t)l * HH * 2 * HH;
        const float* Uht_l = U_ht + (size_t)l * HH * HH;

        for (int t = 0; t < TT; t++) {
            k_phaseA<<<dim3(32, 4), 128>>>(Uh_l, t);
            k_phaseB<<<dim3(32, 4), 128>>>(Uht_l, t);
        }

        // h_final for this layer
        if ((long long)out_size >= need)
            cudaMemcpyAsync(out + (size_t)TT * BB * VV + (size_t)l * BB * HH, p_hcur,
                            (size_t)BB * HH * sizeof(float), cudaMemcpyDeviceToDevice);

        // batched non-recurrent fc: inp = h_all @ fc_W[l]^T + fc_b[l]
        k_gemm<true><<<dim3(HH / 64, MALL / 128), 256>>>(
            p_hall, fc_W + (size_t)l * HH * HH, fc_b + (size_t)l * HH,
            p_inp, MALL, HH, HH);

        // gates_x for layer 1 (depends on layer-0 fc output)
        if (l == 0) {
            k_gemm<false><<<dim3((3 * HH) / 64, MALL / 128), 256>>>(
                p_inp, W_x + (size_t)HH * 3 * HH, b_rzh + 3 * HH,
                p_gx, MALL, 3 * HH, HH);
        }
    }

    // decoder: logits = inp @ dec_W^T + dec_b
    k_gemm<true><<<dim3((VV + 63) / 64, MALL / 128), 256>>>(
        p_inp, dec_W, dec_b, out, MALL, VV, HH);
}

// round 4
// speedup vs baseline: 1.4367x; 1.4367x over previous
#include <cuda_runtime.h>
#include <math.h>
#include <stdint.h>

// ---------------------------------------------------------------------------
// GRU LM: T=128, B=64, E=H=512, V=10000, 2 layers.
// Round 2: persistent per-layer recurrence kernel (weights SMEM-resident,
// cp.async staged h/rh, custom grid barrier). Big GEMMs unchanged.
// ---------------------------------------------------------------------------

#define TT   128
#define BB   64
#define HH   512
#define VV   10000
#define MALL (TT * BB)   // 8192

#define NBLK   128          // persistent blocks (1 per SM, all resident)
#define NTHR   256
#define STRIDE 516          // sStage row stride (floats), float4-aligned pad

// scratch (device globals: no allocation allowed)
__device__ float g_emb [MALL * HH];
__device__ float g_gx  [MALL * 3 * HH];
__device__ float g_inp [MALL * HH];
__device__ float g_hall[MALL * HH];
__device__ float g_hcur[BB * HH];
__device__ float g_z   [BB * HH];
__device__ float g_rh  [BB * HH];

// grid barrier state
__device__ unsigned g_bar_cnt = 0;
__device__ unsigned g_bar_gen = 0;

// ---------------------------------------------------------------------------
__global__ void k_gather(const int* __restrict__ inp, const float* __restrict__ tbl) {
    int i   = blockIdx.x;
    int row = inp[i];
    const float4* src = reinterpret_cast<const float4*>(tbl + (size_t)row * HH);
    float4*       dst = reinterpret_cast<float4*>(g_emb + (size_t)i * HH);
    for (int j = threadIdx.x; j < HH / 4; j += blockDim.x) dst[j] = src[j];
}

// ---------------------------------------------------------------------------
// Big fp32 GEMM (unchanged from round 0; known-good)
// ---------------------------------------------------------------------------
template <bool NT>
__global__ __launch_bounds__(256) void k_gemm(const float* __restrict__ A,
                                              const float* __restrict__ Bm,
                                              const float* __restrict__ bias,
                                              float* __restrict__ C,
                                              int M, int N, int K) {
    __shared__ float sA[16][128];
    __shared__ float sB[16][64];
    int tid = threadIdx.x;
    int tx  = tid & 15;
    int ty  = tid >> 4;
    int m0  = blockIdx.y * 128;
    int n0  = blockIdx.x * 64;

    float acc[8][4];
#pragma unroll
    for (int i = 0; i < 8; i++)
#pragma unroll
        for (int j = 0; j < 4; j++) acc[i][j] = 0.f;

    for (int k0 = 0; k0 < K; k0 += 16) {
#pragma unroll
        for (int i = 0; i < 2; i++) {
            int idx = tid + i * 256;
            int r   = idx >> 2;
            int c4  = idx & 3;
            float4 v = *reinterpret_cast<const float4*>(
                &A[(size_t)(m0 + r) * K + k0 + c4 * 4]);
            sA[c4 * 4 + 0][r] = v.x;
            sA[c4 * 4 + 1][r] = v.y;
            sA[c4 * 4 + 2][r] = v.z;
            sA[c4 * 4 + 3][r] = v.w;
        }
        if (!NT) {
            int r  = tid >> 4;
            int c4 = tid & 15;
            int n  = n0 + c4 * 4;
            float4 v = make_float4(0.f, 0.f, 0.f, 0.f);
            if (n < N)
                v = *reinterpret_cast<const float4*>(&Bm[(size_t)(k0 + r) * N + n]);
            *reinterpret_cast<float4*>(&sB[r][c4 * 4]) = v;
        } else {
            int r  = tid >> 2;
            int c4 = tid & 3;
            int n  = n0 + r;
            float4 v = make_float4(0.f, 0.f, 0.f, 0.f);
            if (n < N)
                v = *reinterpret_cast<const float4*>(&Bm[(size_t)n * K + k0 + c4 * 4]);
            sB[c4 * 4 + 0][r] = v.x;
            sB[c4 * 4 + 1][r] = v.y;
            sB[c4 * 4 + 2][r] = v.z;
            sB[c4 * 4 + 3][r] = v.w;
        }
        __syncthreads();

#pragma unroll
        for (int k = 0; k < 16; k++) {
            float4 b  = *reinterpret_cast<float4*>(&sB[k][tx * 4]);
            float4 a0 = *reinterpret_cast<float4*>(&sA[k][ty * 8]);
            float4 a1 = *reinterpret_cast<float4*>(&sA[k][ty * 8 + 4]);
            float av[8] = {a0.x, a0.y, a0.z, a0.w, a1.x, a1.y, a1.z, a1.w};
            float bv[4] = {b.x, b.y, b.z, b.w};
#pragma unroll
            for (int i = 0; i < 8; i++)
#pragma unroll
                for (int j = 0; j < 4; j++) acc[i][j] += av[i] * bv[j];
        }
        __syncthreads();
    }

    int n = n0 + tx * 4;
    if (n < N) {
        float4 bv = make_float4(0.f, 0.f, 0.f, 0.f);
        if (bias) bv = *reinterpret_cast<const float4*>(&bias[n]);
#pragma unroll
        for (int i = 0; i < 8; i++) {
            int row = m0 + ty * 8 + i;
            float4 o;
            o.x = acc[i][0] + bv.x;
            o.y = acc[i][1] + bv.y;
            o.z = acc[i][2] + bv.z;
            o.w = acc[i][3] + bv.w;
            *reinterpret_cast<float4*>(&C[(size_t)row * N + n]) = o;
        }
    }
}

// ---------------------------------------------------------------------------
// cp.async helpers
// ---------------------------------------------------------------------------
__device__ __forceinline__ void cpasync16(float* dst_smem, const float* src) {
    uint32_t d = (uint32_t)__cvta_generic_to_shared(dst_smem);
    asm volatile("cp.async.cg.shared.global [%0], [%1], 16;" :: "r"(d), "l"(src));
}
__device__ __forceinline__ void cp_commit() {
    asm volatile("cp.async.commit_group;");
}
__device__ __forceinline__ void cp_wait1() {
    asm volatile("cp.async.wait_group 1;");
}
__device__ __forceinline__ void cp_wait0() {
    asm volatile("cp.async.wait_group 0;");
}

// grid barrier: all NBLK blocks arrive; last flips generation.
__device__ __forceinline__ void gbar() {
    __syncthreads();
    if (threadIdx.x == 0) {
        volatile unsigned* vgen = &g_bar_gen;
        unsigned gen = *vgen;           // snapshot BEFORE arriving
        __threadfence();                // release prior writes
        unsigned v = atomicAdd(&g_bar_cnt, 1u);
        if (v == (unsigned)(gridDim.x - 1)) {
            g_bar_cnt = 0;
            __threadfence();
            *vgen = gen + 1;
        } else {
            while (*vgen == gen) {
#if __CUDA_ARCH__ >= 700
                __nanosleep(40);
#endif
            }
        }
        __threadfence();
    }
    __syncthreads();
}

// ---------------------------------------------------------------------------
// Persistent recurrence kernel: one launch = one full layer (128 timesteps).
// Block b owns phase-A columns [8b,8b+8) of 1024 and phase-B columns
// [4b,4b+4) of 512. U slices live in SMEM for the whole kernel.
// ---------------------------------------------------------------------------
__global__ __launch_bounds__(NTHR, 1) void k_recur(const float* __restrict__ Uh,
                                                   const float* __restrict__ Uht) {
    extern __shared__ float sm[];
    float* sStage = sm;                      // 64 x STRIDE = 33024 floats
    float* sUh    = sStage + 64 * STRIDE;    // 512 x 8     =  4096
    float* sUht   = sUh + 4096;              // 512 x 4     =  2048
    float* sPart  = sUht + 2048;             // up to 4x64x8 = 2048
    float* sHold  = sPart + 2048;            // 256

    int tid   = threadIdx.x;
    int bid   = blockIdx.x;
    int colA0 = bid * 8;    // in [0,1024)
    int colB0 = bid * 4;    // in [0,512)

    // ---- load weight slices into SMEM (once) ----
    for (int i = tid; i < 512 * 2; i += NTHR) {
        int k = i >> 1, h4 = (i & 1) * 4;
        *reinterpret_cast<float4*>(&sUh[k * 8 + h4]) =
            *reinterpret_cast<const float4*>(&Uh[(size_t)k * (2 * HH) + colA0 + h4]);
    }
    for (int i = tid; i < 512; i += NTHR) {
        *reinterpret_cast<float4*>(&sUht[i * 4]) =
            *reinterpret_cast<const float4*>(&Uht[(size_t)i * HH + colB0]);
    }
    __syncthreads();

    // thread tiling
    const int kseg = tid >> 6;           // 0..3 (K split within each chunk)
    const int r2   = (tid >> 1) & 31;    // phase A row pair
    const int cg   = tid & 1;            // phase A col quad
    const int rowA = r2 * 2;
    const int rowB = tid & 63;           // phase B row

    for (int t = 0; t < TT; t++) {
        // ================= PHASE A =================
        // stage h (64x512) via pipelined cp.async; compute gates_h slice
        {
            const float* src = g_hcur;
            // issue chunk 0
#pragma unroll
            for (int i = 0; i < 8; i++) {
                int idx = tid + i * NTHR;
                int row = idx >> 5, kq = (idx & 31) << 2;
                cpasync16(&sStage[row * STRIDE + kq], src + (size_t)row * HH + kq);
            }
            cp_commit();

            float acc[8];
#pragma unroll
            for (int i = 0; i < 8; i++) acc[i] = 0.f;

            for (int c = 0; c < 4; c++) {
                if (c < 3) {
#pragma unroll
                    for (int i = 0; i < 8; i++) {
                        int idx = tid + i * NTHR;
                        int row = idx >> 5, kq = (idx & 31) << 2;
                        int off = (c + 1) * 128 + kq;
                        cpasync16(&sStage[row * STRIDE + off],
                                  src + (size_t)row * HH + off);
                    }
                    cp_commit();
                    cp_wait1();
                } else {
                    cp_wait0();
                }
                __syncthreads();

                int kb = c * 128 + kseg * 32;
                const float* A0 = &sStage[rowA * STRIDE];
                const float* A1 = A0 + STRIDE;
#pragma unroll
                for (int kk = 0; kk < 32; kk++) {
                    int k = kb + kk;
                    float4 b = *reinterpret_cast<const float4*>(&sUh[k * 8 + cg * 4]);
                    float a0 = A0[k], a1 = A1[k];
                    acc[0] += a0 * b.x; acc[1] += a0 * b.y;
                    acc[2] += a0 * b.z; acc[3] += a0 * b.w;
                    acc[4] += a1 * b.x; acc[5] += a1 * b.y;
                    acc[6] += a1 * b.z; acc[7] += a1 * b.w;
                }
            }

            // reduce K-split partials via SMEM
            *reinterpret_cast<float4*>(&sPart[(kseg * 64 + rowA) * 8 + cg * 4]) =
                make_float4(acc[0], acc[1], acc[2], acc[3]);
            *reinterpret_cast<float4*>(&sPart[(kseg * 64 + rowA + 1) * 8 + cg * 4]) =
                make_float4(acc[4], acc[5], acc[6], acc[7]);
            __syncthreads();

            // epilogue: 512 outputs, 2 per thread
#pragma unroll
            for (int j = 0; j < 2; j++) {
                int o   = tid + j * NTHR;
                int row = o >> 3, col = o & 7;
                float s = sPart[(0 * 64 + row) * 8 + col]
                        + sPart[(1 * 64 + row) * 8 + col]
                        + sPart[(2 * 64 + row) * 8 + col]
                        + sPart[(3 * 64 + row) * 8 + col];
                float pre = g_gx[((size_t)t * BB + row) * (3 * HH) + colA0 + col] + s;
                float sg = 1.f / (1.f + expf(-pre));
                if (colA0 < HH) {
                    int n = colA0 + col;
                    __stcg(&g_rh[row * HH + n], sg * sStage[row * STRIDE + n]);
                } else {
                    int n = colA0 + col - HH;
                    __stcg(&g_z[row * HH + n], sg);
                }
            }
        }
        gbar();   // all rh/z complete

        // save h_prev for our phase-B columns before restaging
        {
            int row = tid >> 2, col = tid & 3;
            sHold[tid] = sStage[row * STRIDE + colB0 + col];
        }
        __syncthreads();

        // ================= PHASE B =================
        {
            const float* src = g_rh;
#pragma unroll
            for (int i = 0; i < 8; i++) {
                int idx = tid + i * NTHR;
                int row = idx >> 5, kq = (idx & 31) << 2;
                cpasync16(&sStage[row * STRIDE + kq], src + (size_t)row * HH + kq);
            }
            cp_commit();

            float acc[4] = {0.f, 0.f, 0.f, 0.f};

            for (int c = 0; c < 4; c++) {
                if (c < 3) {
#pragma unroll
                    for (int i = 0; i < 8; i++) {
                        int idx = tid + i * NTHR;
                        int row = idx >> 5, kq = (idx & 31) << 2;
                        int off = (c + 1) * 128 + kq;
                        cpasync16(&sStage[row * STRIDE + off],
                                  src + (size_t)row * HH + off);
                    }
                    cp_commit();
                    cp_wait1();
                } else {
                    cp_wait0();
                }
                __syncthreads();

                int kb = c * 128 + kseg * 32;
                const float* A0 = &sStage[rowB * STRIDE];
#pragma unroll
                for (int kk = 0; kk < 32; kk++) {
                    int k = kb + kk;
                    float4 b = *reinterpret_cast<const float4*>(&sUht[k * 4]);
                    float a = A0[k];
                    acc[0] += a * b.x; acc[1] += a * b.y;
                    acc[2] += a * b.z; acc[3] += a * b.w;
                }
            }

            *reinterpret_cast<float4*>(&sPart[(kseg * 64 + rowB) * 4]) =
                make_float4(acc[0], acc[1], acc[2], acc[3]);
            __syncthreads();

            // epilogue: 256 outputs, 1 per thread
            {
                int row = tid >> 2, col = tid & 3;
                int n   = colB0 + col;
                float s = sPart[(0 * 64 + row) * 4 + col]
                        + sPart[(1 * 64 + row) * 4 + col]
                        + sPart[(2 * 64 + row) * 4 + col]
                        + sPart[(3 * 64 + row) * 4 + col];
                float pre  = g_gx[((size_t)t * BB + row) * (3 * HH) + 2 * HH + n] + s;
                float htil = tanhf(pre);
                float z  = __ldcg(&g_z[row * HH + n]);
                float hp = sHold[tid];
                float hn = (1.f - z) * hp + z * htil;
                __stcg(&g_hcur[row * HH + n], hn);
                g_hall[((size_t)t * BB + row) * HH + n] = hn;
            }
        }
        gbar();   // h(t) complete before t+1 staging
    }
}

// ---------------------------------------------------------------------------
extern "C" void kernel_launch(void* const* d_in, const int* in_sizes, int n_in,
                              void* d_out, int out_size) {
    const int*   inputs    = (const int*)  d_in[0];
    const float* hidden    = (const float*)d_in[1];
    const float* emb_table = (const float*)d_in[2];
    const float* W_x       = (const float*)d_in[3];
    const float* U_h       = (const float*)d_in[4];
    const float* U_ht      = (const float*)d_in[5];
    const float* b_rzh     = (const float*)d_in[6];
    const float* fc_W      = (const float*)d_in[7];
    const float* fc_b      = (const float*)d_in[8];
    const float* dec_W     = (const float*)d_in[9];
    const float* dec_b     = (const float*)d_in[10];
    float* out = (float*)d_out;

    float *p_emb, *p_gx, *p_inp, *p_hall, *p_hcur;
    cudaGetSymbolAddress((void**)&p_emb,  g_emb);
    cudaGetSymbolAddress((void**)&p_gx,   g_gx);
    cudaGetSymbolAddress((void**)&p_inp,  g_inp);
    cudaGetSymbolAddress((void**)&p_hall, g_hall);
    cudaGetSymbolAddress((void**)&p_hcur, g_hcur);

    static const int SMEM_BYTES = (64 * STRIDE + 4096 + 2048 + 2048 + 256) * 4;
    static bool attr_set = false;
    if (!attr_set) {
        cudaFuncSetAttribute(k_recur, cudaFuncAttributeMaxDynamicSharedMemorySize,
                             SMEM_BYTES);
        attr_set = true;
    }

    // 1) embeddings
    k_gather<<<MALL, 128>>>(inputs, emb_table);

    // 2) gates_x for layer 0
    k_gemm<false><<<dim3((3 * HH) / 64, MALL / 128), 256>>>(
        p_emb, W_x, b_rzh, p_gx, MALL, 3 * HH, HH);

    long long need = (long long)TT * BB * VV + 2LL * BB * HH;

    for (int l = 0; l < 2; l++) {
        cudaMemcpyAsync(p_hcur, hidden + (size_t)l * BB * HH,
                        (size_t)BB * HH * sizeof(float), cudaMemcpyDeviceToDevice);

        // persistent recurrence: whole layer in one launch
        k_recur<<<NBLK, NTHR, SMEM_BYTES>>>(
            U_h  + (size_t)l * HH * 2 * HH,
            U_ht + (size_t)l * HH * HH);

        if ((long long)out_size >= need)
            cudaMemcpyAsync(out + (size_t)TT * BB * VV + (size_t)l * BB * HH, p_hcur,
                            (size_t)BB * HH * sizeof(float), cudaMemcpyDeviceToDevice);

        // batched non-recurrent fc
        k_gemm<true><<<dim3(HH / 64, MALL / 128), 256>>>(
            p_hall, fc_W + (size_t)l * HH * HH, fc_b + (size_t)l * HH,
            p_inp, MALL, HH, HH);

        if (l == 0) {
            k_gemm<false><<<dim3((3 * HH) / 64, MALL / 128), 256>>>(
                p_inp, W_x + (size_t)HH * 3 * HH, b_rzh + 3 * HH,
                p_gx, MALL, 3 * HH, HH);
        }
    }

    // decoder
    k_gemm<true><<<dim3((VV + 63) / 64, MALL / 128), 256>>>(
        p_inp, dec_W, dec_b, out, MALL, VV, HH);
}

// round 7
// speedup vs baseline: 2.0018x; 1.3934x over previous
#include <cuda_runtime.h>
#include <cuda_bf16.h>
#include <math.h>
#include <stdint.h>

// ---------------------------------------------------------------------------
// GRU LM: T=128, B=64, E=H=512, V=10000, 2 layers.
// Round 6: big GEMMs via arch-generic tensor cores (mma.sync bf16, 3-term
// fp32 emulation). tcgen05 is NOT available through this build path
// (.target sm_103 rejects it). Recurrence unchanged (round-2 persistent).
// ---------------------------------------------------------------------------

#define TT   128
#define BB   64
#define HH   512
#define VV   10000
#define MALL (TT * BB)   // 8192
#define GK   512

#define NBLK   128
#define NTHR   256
#define STRIDE 516

// fp32 scratch
__device__ float g_emb [MALL * HH];
__device__ float g_gx  [MALL * 3 * HH];
__device__ float g_inp [MALL * HH];
__device__ float g_hall[MALL * HH];
__device__ float g_hcur[BB * HH];
__device__ float g_z   [BB * HH];
__device__ float g_rh  [BB * HH];
__device__ float g_wxT [2 * 3 * HH * HH];   // W_x transposed to [N][K]

// bf16 hi/lo planes
__device__ __nv_bfloat16 g_ahi [MALL * GK];
__device__ __nv_bfloat16 g_alo [MALL * GK];
__device__ __nv_bfloat16 g_wxh [2 * 3 * HH * HH];
__device__ __nv_bfloat16 g_wxl [2 * 3 * HH * HH];
__device__ __nv_bfloat16 g_fch [2 * HH * HH];
__device__ __nv_bfloat16 g_fcl [2 * HH * HH];
__device__ __nv_bfloat16 g_dech[VV * HH];
__device__ __nv_bfloat16 g_decl[VV * HH];

// grid barrier state
__device__ unsigned g_bar_cnt = 0;
__device__ unsigned g_bar_gen = 0;

// ---------------------------------------------------------------------------
__global__ void k_gather(const int* __restrict__ inp, const float* __restrict__ tbl) {
    int i   = blockIdx.x;
    int row = inp[i];
    const float4* src = reinterpret_cast<const float4*>(tbl + (size_t)row * HH);
    float4*       dst = reinterpret_cast<float4*>(g_emb + (size_t)i * HH);
    for (int j = threadIdx.x; j < HH / 4; j += blockDim.x) dst[j] = src[j];
}

// Transpose W[K][N] -> WT[N][K]
__global__ void k_transpose(const float* __restrict__ W, float* __restrict__ WT,
                            int K, int N) {
    __shared__ float tile[32][33];
    int k0 = blockIdx.y * 32, n0 = blockIdx.x * 32;
    int tx = threadIdx.x, ty = threadIdx.y;
#pragma unroll
    for (int i = 0; i < 32; i += 8)
        if (k0 + ty + i < K && n0 + tx < N)
            tile[ty + i][tx] = W[(size_t)(k0 + ty + i) * N + n0 + tx];
    __syncthreads();
#pragma unroll
    for (int i = 0; i < 32; i += 8)
        if (n0 + ty + i < N && k0 + tx < K)
            WT[(size_t)(n0 + ty + i) * K + k0 + tx] = tile[tx][ty + i];
}

// fp32 -> (hi, lo) bf16 planes. n4 = element count / 4.
__global__ void k_cvt(const float* __restrict__ src,
                      __nv_bfloat16* __restrict__ hi,
                      __nv_bfloat16* __restrict__ lo, int n4) {
    int i = blockIdx.x * blockDim.x + threadIdx.x;
    if (i >= n4) return;
    float4 v = reinterpret_cast<const float4*>(src)[i];
    __nv_bfloat16 h0 = __float2bfloat16(v.x), h1 = __float2bfloat16(v.y),
                  h2 = __float2bfloat16(v.z), h3 = __float2bfloat16(v.w);
    __nv_bfloat16 l0 = __float2bfloat16(v.x - __bfloat162float(h0));
    __nv_bfloat16 l1 = __float2bfloat16(v.y - __bfloat162float(h1));
    __nv_bfloat16 l2 = __float2bfloat16(v.z - __bfloat162float(h2));
    __nv_bfloat16 l3 = __float2bfloat16(v.w - __bfloat162float(h3));
    uint2 hv, lv;
    hv.x = (uint32_t)__bfloat16_as_ushort(h0) | ((uint32_t)__bfloat16_as_ushort(h1) << 16);
    hv.y = (uint32_t)__bfloat16_as_ushort(h2) | ((uint32_t)__bfloat16_as_ushort(h3) << 16);
    lv.x = (uint32_t)__bfloat16_as_ushort(l0) | ((uint32_t)__bfloat16_as_ushort(l1) << 16);
    lv.y = (uint32_t)__bfloat16_as_ushort(l2) | ((uint32_t)__bfloat16_as_ushort(l3) << 16);
    reinterpret_cast<uint2*>(hi)[i] = hv;
    reinterpret_cast<uint2*>(lo)[i] = lv;
}

// ---------------------------------------------------------------------------
// mma.sync helpers (arch-generic, sm_80+)
// ---------------------------------------------------------------------------
__device__ __forceinline__ void cpasync16(void* dst_smem, const void* src) {
    uint32_t d = (uint32_t)__cvta_generic_to_shared(dst_smem);
    asm volatile("cp.async.cg.shared.global [%0], [%1], 16;" :: "r"(d), "l"(src));
}
__device__ __forceinline__ void cpasync16z(void* dst_smem, const void* src, int sz) {
    uint32_t d = (uint32_t)__cvta_generic_to_shared(dst_smem);
    asm volatile("cp.async.cg.shared.global [%0], [%1], 16, %2;"
                 :: "r"(d), "l"(src), "r"(sz));
}
__device__ __forceinline__ void cp_commit() { asm volatile("cp.async.commit_group;"); }

__device__ __forceinline__ void ldmx4(uint32_t* r, uint32_t addr) {
    asm volatile("ldmatrix.sync.aligned.m8n8.x4.shared.b16 {%0,%1,%2,%3}, [%4];"
                 : "=r"(r[0]), "=r"(r[1]), "=r"(r[2]), "=r"(r[3]) : "r"(addr));
}
__device__ __forceinline__ void mma16816(float* d, const uint32_t* a, const uint32_t* b) {
    asm volatile(
        "mma.sync.aligned.m16n8k16.row.col.f32.bf16.bf16.f32 "
        "{%0,%1,%2,%3}, {%4,%5,%6,%7}, {%8,%9}, {%0,%1,%2,%3};"
        : "+f"(d[0]), "+f"(d[1]), "+f"(d[2]), "+f"(d[3])
        : "r"(a[0]), "r"(a[1]), "r"(a[2]), "r"(a[3]), "r"(b[0]), "r"(b[1]));
}

// ---------------------------------------------------------------------------
// Tensor-core GEMM: C[M,N] = A[M,512] @ B[N,512]^T + bias (fp32 via bf16x3).
// K-sequence: 3 phases x 512 over (Ahi,Bhi), (Alo,Bhi), (Ahi,Blo).
// CTA 128x128, BK=32, 256 threads (8 warps, 2x4), double-buffered cp.async.
// SMEM rows: 32 bf16 = 64B, XOR swizzle seg' = seg ^ ((row>>1)&3).
// ---------------------------------------------------------------------------
#define NCH 48   // 3 phases * 512/32

__global__ __launch_bounds__(256)
void k_gemm_tc(const __nv_bfloat16* __restrict__ Ahi,
               const __nv_bfloat16* __restrict__ Alo,
               const __nv_bfloat16* __restrict__ Bhi,
               const __nv_bfloat16* __restrict__ Blo,
               const float* __restrict__ bias, float* __restrict__ C, int N) {
    __shared__ __align__(16) char smem[2 * 16384];  // per stage: A 8KB + B 8KB

    const int tid  = threadIdx.x;
    const int lane = tid & 31;
    const int wid  = tid >> 5;
    const int wm   = wid >> 2;          // 0..1  (64 rows)
    const int wn   = wid & 3;           // 0..3  (32 cols)
    const int m0   = blockIdx.y * 128;
    const int n0   = blockIdx.x * 128;

    // cp.async thread mapping (per 16B segment)
    const int sRow0 = tid >> 2;                 // rows 0..63   (seg i=0)
    const int sC16  = tid & 3;
    const int sSw0  = sC16 ^ ((sRow0 >> 1) & 3);
    const int sRow1 = sRow0 + 64;               // rows 64..127 (seg i=1)
    const int sSw1  = sC16 ^ ((sRow1 >> 1) & 3);

    // ldmatrix per-lane bases
    const int aRow16 = lane & 15;
    const int aKhalf = lane >> 4;
    const int bL8 = lane & 7, bG = lane >> 3;

    int  aRowOff[4], aXor[4];
#pragma unroll
    for (int mt = 0; mt < 4; mt++) {
        int r = wm * 64 + mt * 16 + aRow16;
        aRowOff[mt] = r * 64;
        aXor[mt]    = (r >> 1) & 3;
    }
    int  bRowOff[2], bXor[2];
#pragma unroll
    for (int p = 0; p < 2; p++) {
        int r = wn * 32 + p * 16 + ((bG >> 1) << 3) + bL8;
        bRowOff[p] = r * 64;
        bXor[p]    = (r >> 1) & 3;
    }
    const uint32_t smemBase = (uint32_t)__cvta_generic_to_shared(smem);

    float acc[4][4][4];
#pragma unroll
    for (int i = 0; i < 4; i++)
#pragma unroll
        for (int j = 0; j < 4; j++)
#pragma unroll
            for (int q = 0; q < 4; q++) acc[i][j][q] = 0.f;

    // --- chunk issue ---
    auto issue = [&](int c) {
        int phase = c >> 4;
        int k0    = (c & 15) * 32;
        const __nv_bfloat16* Ap = (phase == 1) ? Alo : Ahi;
        const __nv_bfloat16* Bp = (phase == 2) ? Blo : Bhi;
        char* sA = smem + (c & 1) * 16384;
        char* sB = sA + 8192;
        // A: rows 0..127, this thread: 2 segments
        cpasync16(sA + sRow0 * 64 + sSw0 * 16,
                  Ap + (size_t)(m0 + sRow0) * GK + k0 + sC16 * 8);
        cpasync16(sA + sRow1 * 64 + sSw1 * 16,
                  Ap + (size_t)(m0 + sRow1) * GK + k0 + sC16 * 8);
        // B: rows = n, guarded (zero-fill OOB)
        int nA = n0 + sRow0, nB = n0 + sRow1;
        int cA = nA < N ? nA : N - 1, cB = nB < N ? nB : N - 1;
        cpasync16z(sB + sRow0 * 64 + sSw0 * 16,
                   Bp + (size_t)cA * GK + k0 + sC16 * 8, nA < N ? 16 : 0);
        cpasync16z(sB + sRow1 * 64 + sSw1 * 16,
                   Bp + (size_t)cB * GK + k0 + sC16 * 8, nB < N ? 16 : 0);
        cp_commit();
    };

    issue(0);
    issue(1);

    for (int c = 0; c < NCH; c++) {
        if (c < NCH - 1) asm volatile("cp.async.wait_group 1;");
        else             asm volatile("cp.async.wait_group 0;");
        __syncthreads();

        uint32_t sAb = smemBase + (c & 1) * 16384;
        uint32_t sBb = sAb + 8192;

#pragma unroll
        for (int k16 = 0; k16 < 2; k16++) {
            int segA = k16 * 2 + aKhalf;
            int segB = k16 * 2 + (bG & 1);
            uint32_t af[4][4], bf[2][4];
#pragma unroll
            for (int mt = 0; mt < 4; mt++)
                ldmx4(af[mt], sAb + aRowOff[mt] + ((segA ^ aXor[mt]) << 4));
#pragma unroll
            for (int p = 0; p < 2; p++)
                ldmx4(bf[p], sBb + bRowOff[p] + ((segB ^ bXor[p]) << 4));
#pragma unroll
            for (int mt = 0; mt < 4; mt++)
#pragma unroll
                for (int nt = 0; nt < 4; nt++)
                    mma16816(acc[mt][nt], af[mt], &bf[nt >> 1][(nt & 1) * 2]);
        }
        __syncthreads();
        if (c + 2 < NCH) issue(c + 2);
    }

    // --- epilogue ---
    const int quad = lane >> 2, tq = lane & 3;
#pragma unroll
    for (int mt = 0; mt < 4; mt++) {
        int m = m0 + wm * 64 + mt * 16 + quad;
#pragma unroll
        for (int nt = 0; nt < 4; nt++) {
            int n = n0 + wn * 32 + nt * 8 + tq * 2;
            if (n < N) {
                float2 bv = *reinterpret_cast<const float2*>(&bias[n]);
                float2 o0, o1;
                o0.x = acc[mt][nt][0] + bv.x;
                o0.y = acc[mt][nt][1] + bv.y;
                o1.x = acc[mt][nt][2] + bv.x;
                o1.y = acc[mt][nt][3] + bv.y;
                *reinterpret_cast<float2*>(&C[(size_t)m * N + n]) = o0;
                *reinterpret_cast<float2*>(&C[(size_t)(m + 8) * N + n]) = o1;
            }
        }
    }
}

// ---------------------------------------------------------------------------
// grid barrier + persistent recurrence (unchanged from round 2)
// ---------------------------------------------------------------------------
__device__ __forceinline__ void cp_wait1() { asm volatile("cp.async.wait_group 1;"); }
__device__ __forceinline__ void cp_wait0() { asm volatile("cp.async.wait_group 0;"); }

__device__ __forceinline__ void gbar() {
    __syncthreads();
    if (threadIdx.x == 0) {
        volatile unsigned* vgen = &g_bar_gen;
        unsigned gen = *vgen;
        __threadfence();
        unsigned v = atomicAdd(&g_bar_cnt, 1u);
        if (v == (unsigned)(gridDim.x - 1)) {
            g_bar_cnt = 0;
            __threadfence();
            *vgen = gen + 1;
        } else {
            while (*vgen == gen) {
#if __CUDA_ARCH__ >= 700
                __nanosleep(40);
#endif
            }
        }
        __threadfence();
    }
    __syncthreads();
}

__global__ __launch_bounds__(NTHR, 1) void k_recur(const float* __restrict__ Uh,
                                                   const float* __restrict__ Uht) {
    extern __shared__ float smf[];
    float* sStage = smf;
    float* sUh    = sStage + 64 * STRIDE;
    float* sUht   = sUh + 4096;
    float* sPart  = sUht + 2048;
    float* sHold  = sPart + 2048;

    int tid   = threadIdx.x;
    int bid   = blockIdx.x;
    int colA0 = bid * 8;
    int colB0 = bid * 4;

    for (int i = tid; i < 512 * 2; i += NTHR) {
        int k = i >> 1, h4 = (i & 1) * 4;
        *reinterpret_cast<float4*>(&sUh[k * 8 + h4]) =
            *reinterpret_cast<const float4*>(&Uh[(size_t)k * (2 * HH) + colA0 + h4]);
    }
    for (int i = tid; i < 512; i += NTHR) {
        *reinterpret_cast<float4*>(&sUht[i * 4]) =
            *reinterpret_cast<const float4*>(&Uht[(size_t)i * HH + colB0]);
    }
    __syncthreads();

    const int kseg = tid >> 6;
    const int r2   = (tid >> 1) & 31;
    const int cg   = tid & 1;
    const int rowA = r2 * 2;
    const int rowB = tid & 63;

    for (int t = 0; t < TT; t++) {
        // ---- PHASE A ----
        {
            const float* src = g_hcur;
#pragma unroll
            for (int i = 0; i < 8; i++) {
                int idx = tid + i * NTHR;
                int row = idx >> 5, kq = (idx & 31) << 2;
                cpasync16(&sStage[row * STRIDE + kq], src + (size_t)row * HH + kq);
            }
            cp_commit();

            float acc[8];
#pragma unroll
            for (int i = 0; i < 8; i++) acc[i] = 0.f;

            for (int c = 0; c < 4; c++) {
                if (c < 3) {
#pragma unroll
                    for (int i = 0; i < 8; i++) {
                        int idx = tid + i * NTHR;
                        int row = idx >> 5, kq = (idx & 31) << 2;
                        int off = (c + 1) * 128 + kq;
                        cpasync16(&sStage[row * STRIDE + off],
                                  src + (size_t)row * HH + off);
                    }
                    cp_commit();
                    cp_wait1();
                } else {
                    cp_wait0();
                }
                __syncthreads();

                int kb = c * 128 + kseg * 32;
                const float* A0 = &sStage[rowA * STRIDE];
                const float* A1 = A0 + STRIDE;
#pragma unroll
                for (int kk = 0; kk < 32; kk++) {
                    int k = kb + kk;
                    float4 b = *reinterpret_cast<const float4*>(&sUh[k * 8 + cg * 4]);
                    float a0 = A0[k], a1 = A1[k];
                    acc[0] += a0 * b.x; acc[1] += a0 * b.y;
                    acc[2] += a0 * b.z; acc[3] += a0 * b.w;
                    acc[4] += a1 * b.x; acc[5] += a1 * b.y;
                    acc[6] += a1 * b.z; acc[7] += a1 * b.w;
                }
            }

            *reinterpret_cast<float4*>(&sPart[(kseg * 64 + rowA) * 8 + cg * 4]) =
                make_float4(acc[0], acc[1], acc[2], acc[3]);
            *reinterpret_cast<float4*>(&sPart[(kseg * 64 + rowA + 1) * 8 + cg * 4]) =
                make_float4(acc[4], acc[5], acc[6], acc[7]);
            __syncthreads();

#pragma unroll
            for (int j = 0; j < 2; j++) {
                int o   = tid + j * NTHR;
                int row = o >> 3, col = o & 7;
                float s = sPart[(0 * 64 + row) * 8 + col]
                        + sPart[(1 * 64 + row) * 8 + col]
                        + sPart[(2 * 64 + row) * 8 + col]
                        + sPart[(3 * 64 + row) * 8 + col];
                float pre = g_gx[((size_t)t * BB + row) * (3 * HH) + colA0 + col] + s;
                float sg = 1.f / (1.f + expf(-pre));
                if (colA0 < HH) {
                    int n = colA0 + col;
                    __stcg(&g_rh[row * HH + n], sg * sStage[row * STRIDE + n]);
                } else {
                    int n = colA0 + col - HH;
                    __stcg(&g_z[row * HH + n], sg);
                }
            }
        }
        gbar();

        {
            int row = tid >> 2, col = tid & 3;
            sHold[tid] = sStage[row * STRIDE + colB0 + col];
        }
        __syncthreads();

        // ---- PHASE B ----
        {
            const float* src = g_rh;
#pragma unroll
            for (int i = 0; i < 8; i++) {
                int idx = tid + i * NTHR;
                int row = idx >> 5, kq = (idx & 31) << 2;
                cpasync16(&sStage[row * STRIDE + kq], src + (size_t)row * HH + kq);
            }
            cp_commit();

            float acc[4] = {0.f, 0.f, 0.f, 0.f};

            for (int c = 0; c < 4; c++) {
                if (c < 3) {
#pragma unroll
                    for (int i = 0; i < 8; i++) {
                        int idx = tid + i * NTHR;
                        int row = idx >> 5, kq = (idx & 31) << 2;
                        int off = (c + 1) * 128 + kq;
                        cpasync16(&sStage[row * STRIDE + off],
                                  src + (size_t)row * HH + off);
                    }
                    cp_commit();
                    cp_wait1();
                } else {
                    cp_wait0();
                }
                __syncthreads();

                int kb = c * 128 + kseg * 32;
                const float* A0 = &sStage[rowB * STRIDE];
#pragma unroll
                for (int kk = 0; kk < 32; kk++) {
                    int k = kb + kk;
                    float4 b = *reinterpret_cast<const float4*>(&sUht[k * 4]);
                    float a = A0[k];
                    acc[0] += a * b.x; acc[1] += a * b.y;
                    acc[2] += a * b.z; acc[3] += a * b.w;
                }
            }

            *reinterpret_cast<float4*>(&sPart[(kseg * 64 + rowB) * 4]) =
                make_float4(acc[0], acc[1], acc[2], acc[3]);
            __syncthreads();

            {
                int row = tid >> 2, col = tid & 3;
                int n   = colB0 + col;
                float s = sPart[(0 * 64 + row) * 4 + col]
                        + sPart[(1 * 64 + row) * 4 + col]
                        + sPart[(2 * 64 + row) * 4 + col]
                        + sPart[(3 * 64 + row) * 4 + col];
                float pre  = g_gx[((size_t)t * BB + row) * (3 * HH) + 2 * HH + n] + s;
                float htil = tanhf(pre);
                float z  = __ldcg(&g_z[row * HH + n]);
                float hp = sHold[tid];
                float hn = (1.f - z) * hp + z * htil;
                __stcg(&g_hcur[row * HH + n], hn);
                g_hall[((size_t)t * BB + row) * HH + n] = hn;
            }
        }
        gbar();
    }
}

// ---------------------------------------------------------------------------
extern "C" void kernel_launch(void* const* d_in, const int* in_sizes, int n_in,
                              void* d_out, int out_size) {
    const int*   inputs    = (const int*)  d_in[0];
    const float* hidden    = (const float*)d_in[1];
    const float* emb_table = (const float*)d_in[2];
    const float* W_x       = (const float*)d_in[3];
    const float* U_h       = (const float*)d_in[4];
    const float* U_ht      = (const float*)d_in[5];
    const float* b_rzh     = (const float*)d_in[6];
    const float* fc_W      = (const float*)d_in[7];
    const float* fc_b      = (const float*)d_in[8];
    const float* dec_W     = (const float*)d_in[9];
    const float* dec_b     = (const float*)d_in[10];
    float* out = (float*)d_out;

    float *p_emb, *p_gx, *p_inp, *p_hall, *p_hcur, *p_wxT;
    cudaGetSymbolAddress((void**)&p_emb,  g_emb);
    cudaGetSymbolAddress((void**)&p_gx,   g_gx);
    cudaGetSymbolAddress((void**)&p_inp,  g_inp);
    cudaGetSymbolAddress((void**)&p_hall, g_hall);
    cudaGetSymbolAddress((void**)&p_hcur, g_hcur);
    cudaGetSymbolAddress((void**)&p_wxT,  g_wxT);

    __nv_bfloat16 *p_ahi, *p_alo, *p_wxh, *p_wxl, *p_fch, *p_fcl, *p_dech, *p_decl;
    cudaGetSymbolAddress((void**)&p_ahi,  g_ahi);
    cudaGetSymbolAddress((void**)&p_alo,  g_alo);
    cudaGetSymbolAddress((void**)&p_wxh,  g_wxh);
    cudaGetSymbolAddress((void**)&p_wxl,  g_wxl);
    cudaGetSymbolAddress((void**)&p_fch,  g_fch);
    cudaGetSymbolAddress((void**)&p_fcl,  g_fcl);
    cudaGetSymbolAddress((void**)&p_dech, g_dech);
    cudaGetSymbolAddress((void**)&p_decl, g_decl);

    const int RECUR_SMEM = (64 * STRIDE + 4096 + 2048 + 2048 + 256) * 4;
    cudaFuncSetAttribute(k_recur, cudaFuncAttributeMaxDynamicSharedMemorySize,
                         RECUR_SMEM);

    // 0) weight prep: transpose W_x; convert all weights to bf16 planes
    for (int l = 0; l < 2; l++)
        k_transpose<<<dim3(48, 16), dim3(32, 8)>>>(
            W_x + (size_t)l * HH * 3 * HH, p_wxT + (size_t)l * 3 * HH * HH,
            HH, 3 * HH);
    {
        int n4;
        n4 = 2 * 3 * HH * HH / 4;
        k_cvt<<<(n4 + 255) / 256, 256>>>(p_wxT, p_wxh, p_wxl, n4);
        n4 = 2 * HH * HH / 4;
        k_cvt<<<(n4 + 255) / 256, 256>>>(fc_W, p_fch, p_fcl, n4);
        n4 = VV * HH / 4;
        k_cvt<<<(n4 + 255) / 256, 256>>>(dec_W, p_dech, p_decl, n4);
    }

    // 1) embeddings + convert
    k_gather<<<MALL, 128>>>(inputs, emb_table);
    k_cvt<<<(MALL * HH / 4 + 255) / 256, 256>>>(p_emb, p_ahi, p_alo, MALL * HH / 4);

    // 2) gates_x for layer 0
    k_gemm_tc<<<dim3((3 * HH) / 128, MALL / 128), 256>>>(
        p_ahi, p_alo, p_wxh, p_wxl, b_rzh, p_gx, 3 * HH);

    long long need = (long long)TT * BB * VV + 2LL * BB * HH;

    for (int l = 0; l < 2; l++) {
        cudaMemcpyAsync(p_hcur, hidden + (size_t)l * BB * HH,
                        (size_t)BB * HH * sizeof(float), cudaMemcpyDeviceToDevice);

        k_recur<<<NBLK, NTHR, RECUR_SMEM>>>(
            U_h  + (size_t)l * HH * 2 * HH,
            U_ht + (size_t)l * HH * HH);

        if ((long long)out_size >= need)
            cudaMemcpyAsync(out + (size_t)TT * BB * VV + (size_t)l * BB * HH, p_hcur,
                            (size_t)BB * HH * sizeof(float), cudaMemcpyDeviceToDevice);

        // fc: inp = h_all @ fc_W[l]^T + fc_b[l]
        k_cvt<<<(MALL * HH / 4 + 255) / 256, 256>>>(p_hall, p_ahi, p_alo,
                                                    MALL * HH / 4);
        k_gemm_tc<<<dim3(HH / 128, MALL / 128), 256>>>(
            p_ahi, p_alo,
            p_fch + (size_t)l * HH * HH, p_fcl + (size_t)l * HH * HH,
            fc_b + (size_t)l * HH, p_inp, HH);

        // convert fc output for the next consumer (gates_x l1 or decoder)
        k_cvt<<<(MALL * HH / 4 + 255) / 256, 256>>>(p_inp, p_ahi, p_alo,
                                                    MALL * HH / 4);
        if (l == 0) {
            k_gemm_tc<<<dim3((3 * HH) / 128, MALL / 128), 256>>>(
                p_ahi, p_alo,
                p_wxh + (size_t)3 * HH * HH, p_wxl + (size_t)3 * HH * HH,
                b_rzh + 3 * HH, p_gx, 3 * HH);
        }
    }

    // decoder: logits = inp @ dec_W^T + dec_b
    k_gemm_tc<<<dim3((VV + 127) / 128, MALL / 128), 256>>>(
        p_ahi, p_alo, p_dech, p_decl, dec_b, out, VV);
}